// round 11
// baseline (speedup 1.0000x reference)
#include <cuda_runtime.h>
#include <cstdint>
#include <cstddef>

// ---------------------------------------------------------------------------
// 2-layer GraphSAGE mean-aggregator + segment sum + SELU readout.
//
// R11: ONE persistent kernel, three phases separated by software grid
// barriers (all CTAs co-resident: grid = SM count, 1 CTA/SM by smem):
//   Phase 1: warp-specialized 3-slot mbarrier ring (producers stream h2/h1/h0,
//            consumers GEMM w0 + relu [+ mean10]) -> g_ma12, g_a01.
//   Phase 2: seg += relu([a01|ma12] @ w1 + b1), 68 rows/CTA over all CTAs,
//            K=256 as two K=128 passes (Ws reloaded, L2-hot), atomics.
//   Phase 3: readout MLP, CTAs 0..63 (one per graph).
// Grid barriers are epoch-based (monotonic counters -> graph-replay safe).
// ---------------------------------------------------------------------------

static constexpr int NN  = 10000;
static constexpr int DIM = 64;
static constexpr int G   = 64;

__device__ float g_ma12[NN * 128];
__device__ float g_a01 [NN * 128];
__device__ float g_seg [G * 128];
__device__ unsigned g_bar1 = 0;
__device__ unsigned g_bar2 = 0;

// ---------------------------------------------------------------------------
__device__ __forceinline__ void fma2(unsigned long long& a,
                                     unsigned long long x, unsigned long long w) {
    asm("fma.rn.f32x2 %0, %1, %2, %3;" : "=l"(a) : "l"(x), "l"(w), "l"(a));
}
__device__ __forceinline__ void fadd2(unsigned long long& a, unsigned long long b) {
    asm("add.rn.f32x2 %0, %1, %2;" : "=l"(a) : "l"(a), "l"(b));
}
__device__ __forceinline__ unsigned long long fmul2(unsigned long long a,
                                                    unsigned long long b) {
    unsigned long long r;
    asm("mul.rn.f32x2 %0, %1, %2;" : "=l"(r) : "l"(a), "l"(b));
    return r;
}
__device__ __forceinline__ unsigned long long pack2(float x) {
    unsigned long long r;
    asm("mov.b64 %0, {%1, %1};" : "=l"(r) : "f"(x));
    return r;
}
__device__ __forceinline__ void unpack2(unsigned long long v, float& lo, float& hi) {
    asm("mov.b64 {%0, %1}, %2;" : "=f"(lo), "=f"(hi) : "l"(v));
}
__device__ __forceinline__ float selu_f(float x) {
    const float SC = 1.0507009873554805f;
    const float AL = 1.6732632423543772f;
    return SC * (x > 0.0f ? x : AL * (expf(x) - 1.0f));
}

// ---- mbarrier helpers ----
__device__ __forceinline__ uint32_t smem_u32(const void* p) {
    uint32_t a;
    asm("{ .reg .u64 t; cvta.to.shared.u64 t, %1; cvt.u32.u64 %0, t; }"
        : "=r"(a) : "l"(p));
    return a;
}
__device__ __forceinline__ void mbar_init(uint32_t addr, uint32_t count) {
    asm volatile("mbarrier.init.shared.b64 [%0], %1;" :: "r"(addr), "r"(count)
                 : "memory");
}
__device__ __forceinline__ void mbar_arrive(uint32_t addr) {
    asm volatile("mbarrier.arrive.shared.b64 _, [%0];" :: "r"(addr) : "memory");
}
__device__ __forceinline__ void mbar_wait(uint32_t addr, uint32_t parity) {
    asm volatile(
        "{\n\t"
        ".reg .pred P1;\n\t"
        "WAIT_LOOP_%=:\n\t"
        "mbarrier.try_wait.parity.acquire.cta.shared::cta.b64 P1, [%0], %1, 0x989680;\n\t"
        "@P1 bra.uni WAIT_DONE_%=;\n\t"
        "bra.uni WAIT_LOOP_%=;\n\t"
        "WAIT_DONE_%=:\n\t"
        "}"
        :: "r"(addr), "r"(parity) : "memory");
}

// ---- epoch-based software grid barrier (all CTAs co-resident) ----
__device__ __forceinline__ void grid_barrier(unsigned* bar) {
    __threadfence();
    __syncthreads();
    if (threadIdx.x == 0) {
        unsigned ticket = atomicAdd(bar, 1u);
        unsigned target = (ticket / gridDim.x + 1u) * gridDim.x;
        unsigned v;
        do {
            asm volatile("ld.acquire.gpu.u32 %0, [%1];"
                         : "=r"(v) : "l"(bar) : "memory");
        } while (v < target);
    }
    __syncthreads();
}

// One k-group (4 k) of the R-row x 8-col GEMM (cols tx*4.., 64+tx*4..).
template <int KP, int R>
__device__ __forceinline__ void kgroupR(const float* __restrict__ Xp,
                                        const float* __restrict__ WA,
                                        const float* __restrict__ WB,
                                        int g, unsigned long long (&acc2)[R][4]) {
    float4 x4[R];
#pragma unroll
    for (int r = 0; r < R; r++) x4[r] = *(const float4*)(Xp + r * KP + g * 4);
#pragma unroll
    for (int kk = 0; kk < 4; kk++) {
        ulonglong2 wa = *(const ulonglong2*)(WA + (g * 4 + kk) * 128);
        ulonglong2 wb = *(const ulonglong2*)(WB + (g * 4 + kk) * 128);
#pragma unroll
        for (int r = 0; r < R; r++) {
            float xs = kk == 0 ? x4[r].x : kk == 1 ? x4[r].y
                     : kk == 2 ? x4[r].z : x4[r].w;
            unsigned long long xx = pack2(xs);
            fma2(acc2[r][0], xx, wa.x);
            fma2(acc2[r][1], xx, wa.y);
            fma2(acc2[r][2], xx, wb.x);
            fma2(acc2[r][3], xx, wb.y);
        }
    }
}

template <int K, int KP, int R>
__device__ __forceinline__ void gemm_core(const float* __restrict__ Xs,
                                          const float* __restrict__ Ws,
                                          int tx, int ty,
                                          unsigned long long (&acc2)[R][4]) {
    const float* Xp = Xs + ty * R * KP;
    const float* WA = Ws + tx * 4;
    const float* WB = Ws + 64 + tx * 4;
#pragma unroll 4
    for (int g = 0; g < K / 4; g++) kgroupR<KP, R>(Xp, WA, WB, g, acc2);
}

// ---------------------------------------------------------------------------
// Unified persistent kernel. grid = SM count, 640 threads, 1 CTA/SM.
// smem: Xs[3] 80x132 (126720 B) + Ws 128x128 (65536 B) + 6 mbarriers (48 B).
// ---------------------------------------------------------------------------
static constexpr int K1_SLOT  = 80 * 132;
static constexpr int K1_BAROF = (3 * K1_SLOT + 128 * 128) * 4;
static constexpr int NT_A12   = 1250;   // 100000/80
static constexpr int NT_A01   = 125;    // 10000/80
static constexpr int NT_TOT   = NT_A12 + NT_A01;

__global__ void __launch_bounds__(640, 1)
k_all(const float* __restrict__ h0, const float* __restrict__ h1,
      const float* __restrict__ h2,
      const float* __restrict__ w0, const float* __restrict__ b0,
      const float* __restrict__ w1, const float* __restrict__ b1,
      const float* __restrict__ wr1, const float* __restrict__ br1,
      const float* __restrict__ wr2, const float* __restrict__ br2,
      const float* __restrict__ wr3, const float* __restrict__ br3,
      const int* __restrict__ gid, float* __restrict__ outp, int n) {
    extern __shared__ float smem[];
    float* Ws = smem + 3 * K1_SLOT;

    const int tid = threadIdx.x;
    const bool prod = (tid >= 320);
    const uint32_t sb = smem_u32(smem);
    const uint32_t barf = sb + K1_BAROF;
    const uint32_t bare = sb + K1_BAROF + 24;

    if (blockIdx.x == 0) {
        for (int i = tid; i < G * 128; i += 640) g_seg[i] = 0.0f;
    }
    if (tid == 0) {
#pragma unroll
        for (int s = 0; s < 3; s++) {
            mbar_init(barf + s * 8, 320);
            mbar_init(bare + s * 8, 320);
        }
    }

    // producer slot geometry
    const int ptid = prod ? (tid - 320) : 0;
    int r_s[4], c_s[4];
#pragma unroll
    for (int s = 0; s < 4; s++) {
        int idx = ptid + s * 320;
        r_s[s] = idx >> 4;
        c_s[s] = (idx & 15) << 2;
    }

    // consumer geometry + weights
    const int tx = tid & 15, ty = tid >> 4;   // phase-1 consumers: ty 0..19
    float bv[8];
    if (!prod) {
#pragma unroll
        for (int it = 0; it < 13; it++) {
            int i = tid + it * 320;
            if (i < 4096)
                *(float4*)(Ws + i * 4) = *(const float4*)(w0 + i * 4);
        }
#pragma unroll
        for (int j = 0; j < 4; j++) {
            bv[j]     = b0[tx * 4 + j];
            bv[4 + j] = b0[64 + tx * 4 + j];
        }
    }
    __syncthreads();

    // =========================== PHASE 1 ===================================
    const int nt = (NT_TOT - blockIdx.x + gridDim.x - 1) / gridDim.x;

    if (prod) {
        const unsigned long long s04 = pack2(0.04f);
        const unsigned long long s10 = pack2(0.1f);
        int stage = 0, phase = 1;
        for (int i = 0; i < nt; i++) {
            const int t = blockIdx.x + i * gridDim.x;
            mbar_wait(bare + stage * 8, (uint32_t)phase);
            float* Xn = smem + stage * K1_SLOT;

            if (t < NT_A12) {
                const int rb = t * 80;
                const float* h2b = h2 + (size_t)rb * 1600;
                unsigned long long m2[4][2];
#pragma unroll
                for (int s = 0; s < 4; s++) { m2[s][0] = 0ULL; m2[s][1] = 0ULL; }
#pragma unroll 5
                for (int j = 0; j < 25; j++) {
#pragma unroll
                    for (int s = 0; s < 4; s++) {
                        ulonglong2 u = *(const ulonglong2*)(h2b
                            + (size_t)r_s[s] * 1600 + c_s[s] + j * 64);
                        fadd2(m2[s][0], u.x);
                        fadd2(m2[s][1], u.y);
                    }
                }
#pragma unroll
                for (int s = 0; s < 4; s++) {
                    *(ulonglong2*)(Xn + r_s[s] * 132 + 64 + c_s[s]) =
                        make_ulonglong2(fmul2(m2[s][0], s04), fmul2(m2[s][1], s04));
                    *(float4*)(Xn + r_s[s] * 132 + c_s[s]) =
                        *(const float4*)(h1 + (size_t)(rb + r_s[s]) * 64 + c_s[s]);
                }
            } else {
                const int rb = (t - NT_A12) * 80;
                unsigned long long m1[4][2];
#pragma unroll
                for (int s = 0; s < 4; s++) { m1[s][0] = 0ULL; m1[s][1] = 0ULL; }
#pragma unroll
                for (int j = 0; j < 10; j++) {
#pragma unroll
                    for (int s = 0; s < 4; s++) {
                        ulonglong2 u = *(const ulonglong2*)(h1
                            + ((size_t)(rb + r_s[s]) * 10 + j) * 64 + c_s[s]);
                        fadd2(m1[s][0], u.x);
                        fadd2(m1[s][1], u.y);
                    }
                }
#pragma unroll
                for (int s = 0; s < 4; s++) {
                    *(ulonglong2*)(Xn + r_s[s] * 132 + 64 + c_s[s]) =
                        make_ulonglong2(fmul2(m1[s][0], s10), fmul2(m1[s][1], s10));
                    *(float4*)(Xn + r_s[s] * 132 + c_s[s]) =
                        *(const float4*)(h0 + (size_t)(rb + r_s[s]) * 64 + c_s[s]);
                }
            }
            mbar_arrive(barf + stage * 8);
            if (++stage == 3) { stage = 0; phase ^= 1; }
        }
    } else {
        int stage = 0, phase = 0;
        for (int i = 0; i < nt; i++) {
            const int t = blockIdx.x + i * gridDim.x;
            mbar_wait(barf + stage * 8, (uint32_t)phase);
            float* Xc = smem + stage * K1_SLOT;

            unsigned long long acc2[4][4];
#pragma unroll
            for (int r = 0; r < 4; r++)
#pragma unroll
                for (int p = 0; p < 4; p++) acc2[r][p] = 0ULL;

            gemm_core<128, 132, 4>(Xc, Ws, tx, ty, acc2);

            if (t < NT_A12) {
#pragma unroll
                for (int r = 0; r < 4; r++) {
                    float v[8];
#pragma unroll
                    for (int p = 0; p < 4; p++)
                        unpack2(acc2[r][p], v[2 * p], v[2 * p + 1]);
#pragma unroll
                    for (int j = 0; j < 8; j++) {
                        float q = v[j] + bv[j];
                        v[j] = q > 0.0f ? q : 0.0f;
                    }
                    float* dr = Xc + (ty * 4 + r) * 132;
                    *(float4*)(dr + tx * 4)      = make_float4(v[0], v[1], v[2], v[3]);
                    *(float4*)(dr + 64 + tx * 4) = make_float4(v[4], v[5], v[6], v[7]);
                }
                asm volatile("bar.sync 1, 320;" ::: "memory");

#pragma unroll
                for (int it = 0; it < 4; it++) {
                    int o = tid + it * 320;
                    if (o < 1024) {
                        int gl = o >> 7, c = o & 127;
                        float s = 0.0f;
#pragma unroll
                        for (int r2 = 0; r2 < 10; r2++)
                            s += Xc[(gl * 10 + r2) * 132 + c];
                        g_ma12[(size_t)(t * 8 + gl) * 128 + c] = s * 0.1f;
                    }
                }
                mbar_arrive(bare + stage * 8);
            } else {
                mbar_arrive(bare + stage * 8);
                const int rb = (t - NT_A12) * 80;
#pragma unroll
                for (int r = 0; r < 4; r++) {
                    float v[8];
#pragma unroll
                    for (int p = 0; p < 4; p++)
                        unpack2(acc2[r][p], v[2 * p], v[2 * p + 1]);
#pragma unroll
                    for (int j = 0; j < 8; j++) {
                        float q = v[j] + bv[j];
                        v[j] = q > 0.0f ? q : 0.0f;
                    }
                    float* dr = g_a01 + (size_t)(rb + ty * 4 + r) * 128;
                    *(float4*)(dr + tx * 4)      = make_float4(v[0], v[1], v[2], v[3]);
                    *(float4*)(dr + 64 + tx * 4) = make_float4(v[4], v[5], v[6], v[7]);
                }
            }
            if (++stage == 3) { stage = 0; phase ^= 1; }
        }
    }

    // =========================== PHASE 2 ===================================
    grid_barrier(&g_bar1);
    {
        const int rb2 = blockIdx.x * 68;
        float* Xs = smem;   // 68 x 260 = 70720 B (inside the 3 ring slots)

        // stage X = [a01 | ma12] rows rb2..rb2+67 (L2-hot)
#pragma unroll
        for (int it = 0; it < 7; it++) {
            int i = tid + it * 640;
            if (i < 68 * 64) {
                int r = i >> 6, c = (i & 63) << 2;
                int row = rb2 + r;
                float4 v = make_float4(0.f, 0.f, 0.f, 0.f);
                if (row < n) {
                    if (c < 128) v = *(const float4*)(g_a01  + (size_t)row * 128 + c);
                    else         v = *(const float4*)(g_ma12 + (size_t)row * 128 + c - 128);
                }
                *(float4*)(Xs + r * 260 + c) = v;
            }
        }
        // W half 0 (w1 rows 0..127)
#pragma unroll
        for (int it = 0; it < 7; it++) {
            int i = tid + it * 640;
            if (i < 4096)
                *(float4*)(Ws + i * 4) = *(const float4*)(w1 + i * 4);
        }
        __syncthreads();

        unsigned long long acc2[2][4];
#pragma unroll
        for (int r = 0; r < 2; r++)
#pragma unroll
            for (int p = 0; p < 4; p++) acc2[r][p] = 0ULL;

        if (tid < 544)
            gemm_core<128, 260, 2>(Xs, Ws, tx, ty, acc2);
        __syncthreads();

        // W half 1 (w1 rows 128..255)
#pragma unroll
        for (int it = 0; it < 7; it++) {
            int i = tid + it * 640;
            if (i < 4096)
                *(float4*)(Ws + i * 4) = *(const float4*)(w1 + 16384 + i * 4);
        }
        __syncthreads();

        if (tid < 544) {
            gemm_core<128, 260, 2>(Xs + 128, Ws, tx, ty, acc2);

            float bv1[8];
#pragma unroll
            for (int j = 0; j < 4; j++) {
                bv1[j]     = b1[tx * 4 + j];
                bv1[4 + j] = b1[64 + tx * 4 + j];
            }
#pragma unroll
            for (int r = 0; r < 2; r++) {
                int row = rb2 + ty * 2 + r;
                if (row >= n) continue;
                float v[8];
#pragma unroll
                for (int p = 0; p < 4; p++)
                    unpack2(acc2[r][p], v[2 * p], v[2 * p + 1]);
                int g = gid[row];
                float* sp = g_seg + (size_t)g * 128;
#pragma unroll
                for (int j = 0; j < 4; j++) {
                    float q = v[j] + bv1[j];
                    atomicAdd(sp + tx * 4 + j, q > 0.0f ? q : 0.0f);
                }
#pragma unroll
                for (int j = 0; j < 4; j++) {
                    float q = v[4 + j] + bv1[4 + j];
                    atomicAdd(sp + 64 + tx * 4 + j, q > 0.0f ? q : 0.0f);
                }
            }
        }
    }

    // =========================== PHASE 3 ===================================
    grid_barrier(&g_bar2);
    if (blockIdx.x < G && tid < 256) {
        float* w1s  = smem;           // 4480
        float* w2s  = smem + 4480;    // 1225
        float* b1s  = smem + 5705;    // 35
        float* b2s  = smem + 5740;    // 35
        float* w3s  = smem + 5775;    // 35
        float* segs = smem + 5810;    // 128
        float* r1s  = smem + 5938;    // 35
        float* r2s  = smem + 5973;    // 35

        const int g = blockIdx.x;
#pragma unroll
        for (int it = 0; it < 5; it++) {
            int i = tid + it * 256;
            if (i < 1120)
                *(float4*)(w1s + i * 4) = *(const float4*)(wr1 + i * 4);
        }
#pragma unroll
        for (int it = 0; it < 5; it++) {
            int i = tid + it * 256;
            if (i < 1225) w2s[i] = wr2[i];
        }
        if (tid < 35) { b1s[tid] = br1[tid]; b2s[tid] = br2[tid]; w3s[tid] = wr3[tid]; }
        if (tid < 128) segs[tid] = g_seg[g * 128 + tid];
        asm volatile("bar.sync 3, 256;" ::: "memory");

        if (tid < 35) {
            float a0 = 0.f, a1 = 0.f, a2 = 0.f, a3 = 0.f;
#pragma unroll 8
            for (int k = 0; k < 128; k += 4) {
                a0 = fmaf(segs[k],     w1s[(k)     * 35 + tid], a0);
                a1 = fmaf(segs[k + 1], w1s[(k + 1) * 35 + tid], a1);
                a2 = fmaf(segs[k + 2], w1s[(k + 2) * 35 + tid], a2);
                a3 = fmaf(segs[k + 3], w1s[(k + 3) * 35 + tid], a3);
            }
            r1s[tid] = selu_f((a0 + a1) + (a2 + a3) + b1s[tid]);
        }
        asm volatile("bar.sync 3, 256;" ::: "memory");

        if (tid < 35) {
            float a0 = 0.f, a1 = 0.f;
#pragma unroll
            for (int k = 0; k < 34; k += 2) {
                a0 = fmaf(r1s[k],     w2s[(k)     * 35 + tid], a0);
                a1 = fmaf(r1s[k + 1], w2s[(k + 1) * 35 + tid], a1);
            }
            a0 = fmaf(r1s[34], w2s[34 * 35 + tid], a0);
            r2s[tid] = selu_f(a0 + a1 + b2s[tid]) * w3s[tid];
        }
        asm volatile("bar.sync 3, 256;" ::: "memory");

        if (tid == 0) {
            float acc = br3[0];
#pragma unroll
            for (int j = 0; j < 35; j++) acc += r2s[j];
            outp[g] = acc;
        }
    }
}

// ---------------------------------------------------------------------------
extern "C" void kernel_launch(void* const* d_in, const int* in_sizes, int n_in,
                              void* d_out, int out_size) {
    const float* h0  = (const float*)d_in[0];
    const float* h1  = (const float*)d_in[1];
    const float* h2  = (const float*)d_in[2];
    const float* w0  = (const float*)d_in[3];
    const float* b0  = (const float*)d_in[4];
    const float* w1  = (const float*)d_in[5];
    const float* b1  = (const float*)d_in[6];
    const float* wr1 = (const float*)d_in[7];
    const float* br1 = (const float*)d_in[8];
    const float* wr2 = (const float*)d_in[9];
    const float* br2 = (const float*)d_in[10];
    const float* wr3 = (const float*)d_in[11];
    const float* br3 = (const float*)d_in[12];
    const int*   gid = (const int*)d_in[13];

    const int n = in_sizes[0] / DIM;    // 10000

    int dev = 0, nsm = 148;
    cudaGetDevice(&dev);
    cudaDeviceGetAttribute(&nsm, cudaDevAttrMultiProcessorCount, dev);
    // grid = SM count guarantees full co-residency (1 CTA/SM by smem),
    // which the software grid barriers require. Phase 2 needs >= 148 CTAs
    // (148*68 >= 10000); every Blackwell part here has >= 148 SMs.
    if (nsm < 148) nsm = 148;

    constexpr int SMEM_K = K1_BAROF + 48;   // 192304
    cudaFuncSetAttribute((const void*)k_all,
                         cudaFuncAttributeMaxDynamicSharedMemorySize, SMEM_K);

    k_all<<<nsm, 640, SMEM_K>>>(h0, h1, h2, w0, b0, w1, b1,
                                wr1, br1, wr2, br2, wr3, br3,
                                gid, (float*)d_out, n);
}